// round 6
// baseline (speedup 1.0000x reference)
#include <cuda_runtime.h>
#include <cstdint>

#define WDIM 256
#define HDIM 256
#define DPT  8
#define NROWS (2 * DPT * WDIM)          // 4096 hull rows
#define NEG_INF __int_as_float(0xff800000)

// Hull storage: [branch][d][j][w], w fastest for coalesced eval loads.
__device__ float g_hm[2 * DPT * HDIM * WDIM];   // 4 MB
__device__ float g_hb[2 * DPT * HDIM * WDIM];   // 4 MB
__device__ int   g_cnt[2 * DPT * WDIM];

// ───────────────────────── Kernel 1: per-row upper-envelope hulls ──────────
__global__ __launch_bounds__(256)
void hull_kernel(const float* __restrict__ M1, const float* __restrict__ B1,
                 const float* __restrict__ M2, const float* __restrict__ B2)
{
    __shared__ float s_m [8][256];   // sorted slopes per warp
    __shared__ float s_b [8][256];   // sorted intercepts
    __shared__ float s_hx[8][256];   // hull stack x
    __shared__ float s_hy[8][256];   // hull stack y

    const int tid  = threadIdx.x;
    const int wid  = tid >> 5;
    const int lane = tid & 31;
    const int row  = blockIdx.x * 8 + wid;      // 0..4095
    const int br   = row >> 11;
    const int d    = (row >> 8) & 7;
    const int w    = row & 255;

    const float* Msrc = (br ? M2 : M1) + (d * WDIM + w) * HDIM;
    const float* Bsrc = (br ? B2 : B1) + (d * WDIM + w) * HDIM;

    // Load 256 (m,b) pairs: element index e = r*32 + lane
    float m[8], b[8];
#pragma unroll
    for (int r = 0; r < 8; r++) {
        m[r] = Msrc[r * 32 + lane];
        b[r] = Bsrc[r * 32 + lane];
    }

    // In-warp bitonic sort of 256 elements by m ascending.
#pragma unroll
    for (int size = 2; size <= 256; size <<= 1) {
#pragma unroll
        for (int stride = size >> 1; stride > 0; stride >>= 1) {
            if (stride >= 32) {
                const int rs = stride >> 5;
#pragma unroll
                for (int r = 0; r < 8; r++) {
                    const int pr = r ^ rs;
                    if (pr > r) {
                        const bool asc = ((r * 32) & size) == 0;   // lane-uniform
                        const bool sw  = asc ? (m[r] > m[pr]) : (m[r] < m[pr]);
                        if (sw) {
                            float t = m[r]; m[r] = m[pr]; m[pr] = t;
                            t = b[r]; b[r] = b[pr]; b[pr] = t;
                        }
                    }
                }
            } else {
#pragma unroll
                for (int r = 0; r < 8; r++) {
                    const float pm = __shfl_xor_sync(~0u, m[r], stride);
                    const float pb = __shfl_xor_sync(~0u, b[r], stride);
                    const int  e     = r * 32 + lane;
                    const bool lower = (lane & stride) == 0;
                    const bool asc   = (e & size) == 0;
                    const bool take  = (lower == asc) ? (pm < m[r]) : (pm > m[r]);
                    if (take) { m[r] = pm; b[r] = pb; }
                }
            }
        }
    }

#pragma unroll
    for (int r = 0; r < 8; r++) {
        s_m[wid][r * 32 + lane] = m[r];
        s_b[wid][r * 32 + lane] = b[r];
    }
    __syncwarp();

    // Monotone-chain upper hull (lane 0). Double-precision cross products are
    // exact for f32 inputs, so the hull — and hence the evaluated envelope —
    // is exact.
    int k = 0;
    if (lane == 0) {
        for (int i = 0; i < 256; i++) {
            const float pxf = s_m[wid][i], pyf = s_b[wid][i];
            const double px = (double)pxf, py = (double)pyf;
            while (k >= 2) {
                const double ox = (double)s_hx[wid][k - 2];
                const double oy = (double)s_hy[wid][k - 2];
                const double ax = (double)s_hx[wid][k - 1];
                const double ay = (double)s_hy[wid][k - 1];
                if ((ax - ox) * (py - oy) - (ay - oy) * (px - ox) >= 0.0) k--;
                else break;
            }
            s_hx[wid][k] = pxf;
            s_hy[wid][k] = pyf;
            k++;
        }
    }
    __syncwarp();
    k = __shfl_sync(~0u, k, 0);

    const int rb = (br * DPT + d) * WDIM;       // row-block base
    for (int j = lane; j < k; j += 32) {
        g_hm[(rb / WDIM * HDIM + j) * WDIM + w] = s_hx[wid][j];
        g_hb[(rb / WDIM * HDIM + j) * WDIM + w] = s_hy[wid][j];
    }
    if (lane == 0) g_cnt[rb + w] = k;
}

// ───────────────────────── Kernel 2: scan over depth using hulls ──────────
__global__ __launch_bounds__(256)
void scan_kernel(const float* __restrict__ val, float* __restrict__ out)
{
    __shared__ float red[8][16];
    __shared__ float q_s[16];

    const int tid    = threadIdx.x;        // = w row
    const int wid    = tid >> 5;
    const int lane   = tid & 31;
    const int br     = blockIdx.y;
    const int batch0 = blockIdx.x * 16;

    float q[16];
#pragma unroll
    for (int i = 0; i < 16; i++) q[i] = val[batch0 + i];

    for (int d = 0; d < DPT; d++) {
        const int cbase = (br * DPT + d) * WDIM;
        const int k     = g_cnt[cbase + tid];

        // warp-uniform trip count; lanes past their own k contribute -inf
        int kmax = k;
#pragma unroll
        for (int o = 16; o > 0; o >>= 1)
            kmax = max(kmax, __shfl_xor_sync(~0u, kmax, o));

        float acc[16];
#pragma unroll
        for (int i = 0; i < 16; i++) acc[i] = NEG_INF;

        const int hbase = (br * DPT + d) * HDIM * WDIM + tid;
#pragma unroll 2
        for (int j = 0; j < kmax; j++) {
            float mj = g_hm[hbase + j * WDIM];   // coalesced across threads
            float bj = g_hb[hbase + j * WDIM];
            const bool v = (j < k);
            mj = v ? mj : 0.0f;
            bj = v ? bj : NEG_INF;
#pragma unroll
            for (int i = 0; i < 16; i++)
                acc[i] = fmaxf(acc[i], fmaf(q[i], mj, bj));
        }

        // min over w: shfl within warp, then across the 8 warps via smem.
#pragma unroll
        for (int i = 0; i < 16; i++) {
            float v = acc[i];
#pragma unroll
            for (int o = 16; o > 0; o >>= 1)
                v = fminf(v, __shfl_xor_sync(~0u, v, o));
            if (lane == 0) red[wid][i] = v;
        }
        __syncthreads();
        if (tid < 16) {
            float v = red[0][tid];
#pragma unroll
            for (int ww = 1; ww < 8; ww++) v = fminf(v, red[ww][tid]);
            q_s[tid] = v;
        }
        __syncthreads();
#pragma unroll
        for (int i = 0; i < 16; i++) q[i] = q_s[i];
    }

    if (tid < 16)
        out[br * 1024 + batch0 + tid] = q_s[tid];
}

extern "C" void kernel_launch(void* const* d_in, const int* in_sizes, int n_in,
                              void* d_out, int out_size)
{
    const float* val = (const float*)d_in[0];
    const float* M1  = (const float*)d_in[1];
    const float* B1  = (const float*)d_in[2];
    const float* M2  = (const float*)d_in[3];
    const float* B2  = (const float*)d_in[4];
    float* out = (float*)d_out;

    hull_kernel<<<NROWS / 8, 256>>>(M1, B1, M2, B2);
    dim3 grid(1024 / 16, 2);
    scan_kernel<<<grid, 256>>>(val, out);
}

// round 9
// speedup vs baseline: 12.5804x; 12.5804x over previous
#include <cuda_runtime.h>
#include <cstdint>

#define WDIM 256
#define HDIM 256
#define DPT  8
#define NROWS (2 * DPT * WDIM)          // 4096 hull rows
#define NEG_INF __int_as_float(0xff800000)

// Hull storage: [branch*DPT+d][j][w], w fastest for coalesced eval loads.
__device__ float g_hm[2 * DPT * HDIM * WDIM];   // 4 MB
__device__ float g_hb[2 * DPT * HDIM * WDIM];   // 4 MB
__device__ int   g_cnt[2 * DPT * WDIM];

// ───────────────── Kernel 1: per-row upper-envelope hulls (warp/row) ───────
__global__ __launch_bounds__(256)
void hull_kernel(const float* __restrict__ M1, const float* __restrict__ B1,
                 const float* __restrict__ M2, const float* __restrict__ B2)
{
    // Per-warp ping-pong chain buffers: [buf][ m:0..255 | b:256..511 ]
    __shared__ float sbuf[8][2][512];   // 32 KB

    const int tid  = threadIdx.x;
    const int wid  = tid >> 5;
    const int lane = tid & 31;
    const int row  = blockIdx.x * 8 + wid;      // 0..4095
    const int br   = row >> 11;
    const int d    = (row >> 8) & 7;
    const int w    = row & 255;

    const float* Msrc = (br ? M2 : M1) + (d * WDIM + w) * HDIM;
    const float* Bsrc = (br ? B2 : B1) + (d * WDIM + w) * HDIM;

    // Load 256 (m,b) pairs: element index e = r*32 + lane
    float m[8], b[8];
#pragma unroll
    for (int r = 0; r < 8; r++) {
        m[r] = Msrc[r * 32 + lane];
        b[r] = Bsrc[r * 32 + lane];
    }

    // In-warp bitonic sort of 256 elements by m ascending (proven in R5/R6).
#pragma unroll
    for (int size = 2; size <= 256; size <<= 1) {
#pragma unroll
        for (int stride = size >> 1; stride > 0; stride >>= 1) {
            if (stride >= 32) {
                const int rs = stride >> 5;
#pragma unroll
                for (int r = 0; r < 8; r++) {
                    const int pr = r ^ rs;
                    if (pr > r) {
                        const bool asc = ((r * 32) & size) == 0;   // lane-uniform
                        const bool sw  = asc ? (m[r] > m[pr]) : (m[r] < m[pr]);
                        if (sw) {
                            float t = m[r]; m[r] = m[pr]; m[pr] = t;
                            t = b[r]; b[r] = b[pr]; b[pr] = t;
                        }
                    }
                }
            } else {
#pragma unroll
                for (int r = 0; r < 8; r++) {
                    const float pm = __shfl_xor_sync(~0u, m[r], stride);
                    const float pb = __shfl_xor_sync(~0u, b[r], stride);
                    const int  e     = r * 32 + lane;
                    const bool lower = (lane & stride) == 0;
                    const bool asc   = (e & size) == 0;
                    const bool take  = (lower == asc) ? (pm < m[r]) : (pm > m[r]);
                    if (take) { m[r] = pm; b[r] = pb; }
                }
            }
        }
    }

    // Stage sorted chain into buffer 0.
#pragma unroll
    for (int r = 0; r < 8; r++) {
        sbuf[wid][0][r * 32 + lane]       = m[r];
        sbuf[wid][0][256 + r * 32 + lane] = b[r];
    }
    __syncwarp();

    // Iterated convexity sweeps: remove every interior point strictly below
    // the chord of its current neighbors (safe: such a point is strictly
    // below the hull). Exit when no removals -> all triples right-or-straight
    // -> chain is upper-convex (collinear extras harmless in a max).
    int L = 256, cur = 0;
    for (;;) {
        const float* src = sbuf[wid][cur];
        float*       dst = sbuf[wid][cur ^ 1];
        int base = 0;
        const int nr = (L + 31) >> 5;
        for (int r = 0; r < nr; r++) {
            const int idx = r * 32 + lane;
            const bool valid = idx < L;
            float mm = 0.0f, bb = 0.0f;
            bool keep = false;
            if (valid) {
                mm = src[idx];
                bb = src[256 + idx];
                if (idx == 0 || idx == L - 1) {
                    keep = true;
                } else {
                    const double ox = (double)src[idx - 1];
                    const double oy = (double)src[256 + idx - 1];
                    const double px = (double)src[idx + 1];
                    const double py = (double)src[256 + idx + 1];
                    const double ax = (double)mm, ay = (double)bb;
                    const double cr = (ax - ox) * (py - oy)
                                    - (ay - oy) * (px - ox);
                    keep = !(cr > 0.0);     // remove only strictly-below
                }
            }
            const unsigned msk = __ballot_sync(~0u, keep);
            if (keep) {
                const int pos = base + __popc(msk & ((1u << lane) - 1u));
                dst[pos]       = mm;
                dst[256 + pos] = bb;
            }
            base += __popc(msk);
        }
        __syncwarp();
        cur ^= 1;
        if (base == L) break;               // converged: convex chain
        L = base;
    }

    // Write hull lines: layout [blk][j][w], w fastest.
    const int blk = br * DPT + d;
    const float* fin = sbuf[wid][cur];
    for (int j = lane; j < L; j += 32) {
        g_hm[(blk * HDIM + j) * WDIM + w] = fin[j];
        g_hb[(blk * HDIM + j) * WDIM + w] = fin[256 + j];
    }
    if (lane == 0) g_cnt[blk * WDIM + w] = L;
}

// ───────────────── Kernel 2: scan over depth using hulls ───────────────────
#define NB 8
__global__ __launch_bounds__(256)
void scan_kernel(const float* __restrict__ val, float* __restrict__ out)
{
    __shared__ float red[8][NB];
    __shared__ float q_s[NB];

    const int tid    = threadIdx.x;        // = w row
    const int wid    = tid >> 5;
    const int lane   = tid & 31;
    const int br     = blockIdx.y;
    const int batch0 = blockIdx.x * NB;

    float q[NB];
#pragma unroll
    for (int i = 0; i < NB; i++) q[i] = val[batch0 + i];

    for (int d = 0; d < DPT; d++) {
        const int blk = br * DPT + d;
        const int k   = g_cnt[blk * WDIM + tid];

        // warp-uniform trip count; lanes past their own k contribute -inf
        int kmax = k;
#pragma unroll
        for (int o = 16; o > 0; o >>= 1)
            kmax = max(kmax, __shfl_xor_sync(~0u, kmax, o));

        float acc[NB];
#pragma unroll
        for (int i = 0; i < NB; i++) acc[i] = NEG_INF;

        const int hbase = blk * HDIM * WDIM + tid;
#pragma unroll 2
        for (int j = 0; j < kmax; j++) {
            float mj = g_hm[hbase + j * WDIM];   // coalesced across threads
            float bj = g_hb[hbase + j * WDIM];
            const bool v = (j < k);
            mj = v ? mj : 0.0f;
            bj = v ? bj : NEG_INF;
#pragma unroll
            for (int i = 0; i < NB; i++)
                acc[i] = fmaxf(acc[i], fmaf(q[i], mj, bj));
        }

        // min over w: shfl within warp, then across the 8 warps via smem.
#pragma unroll
        for (int i = 0; i < NB; i++) {
            float v = acc[i];
#pragma unroll
            for (int o = 16; o > 0; o >>= 1)
                v = fminf(v, __shfl_xor_sync(~0u, v, o));
            if (lane == 0) red[wid][i] = v;
        }
        __syncthreads();
        if (tid < NB) {
            float v = red[0][tid];
#pragma unroll
            for (int ww = 1; ww < 8; ww++) v = fminf(v, red[ww][tid]);
            q_s[tid] = v;
        }
        __syncthreads();
#pragma unroll
        for (int i = 0; i < NB; i++) q[i] = q_s[i];
    }

    if (tid < NB)
        out[br * 1024 + batch0 + tid] = q_s[tid];
}

extern "C" void kernel_launch(void* const* d_in, const int* in_sizes, int n_in,
                              void* d_out, int out_size)
{
    const float* val = (const float*)d_in[0];
    const float* M1  = (const float*)d_in[1];
    const float* B1  = (const float*)d_in[2];
    const float* M2  = (const float*)d_in[3];
    const float* B2  = (const float*)d_in[4];
    float* out = (float*)d_out;

    hull_kernel<<<NROWS / 8, 256>>>(M1, B1, M2, B2);
    dim3 grid(1024 / NB, 2);
    scan_kernel<<<grid, 256>>>(val, out);
}

// round 10
// speedup vs baseline: 41.1176x; 3.2684x over previous
#include <cuda_runtime.h>
#include <cstdint>

#define WDIM 256
#define HDIM 256
#define DPT  8
#define NROWS (2 * DPT * WDIM)          // 4096 hull rows
#define NEG_INF __int_as_float(0xff800000)
#define POS_INF __int_as_float(0x7f800000)
#define NB 8                            // batches per scan CTA

// Hull storage: [branch*DPT+d][j][w], w fastest for coalesced eval loads.
__device__ float g_hm[2 * DPT * HDIM * WDIM];   // 4 MB
__device__ float g_hb[2 * DPT * HDIM * WDIM];   // 4 MB
__device__ int   g_cnt[2 * DPT * WDIM];

// ─────────── Kernel 1: upper-envelope hull via warp-parallel Jarvis march ───
// Warp per row. 256 (m,b) lines live in registers (8 per lane). March from the
// max-slope line leftward: next hull line = argmax over {m_j < m_cur} of the
// crossing q_j = (b_j - b_cur)/(m_cur - m_j). Slopes strictly decrease each
// step -> terminates in exactly hull-size steps (k ~ 6-12 for Gaussian data).
__global__ __launch_bounds__(256)
void hull_kernel(const float* __restrict__ M1, const float* __restrict__ B1,
                 const float* __restrict__ M2, const float* __restrict__ B2)
{
    const int tid  = threadIdx.x;
    const int wid  = tid >> 5;
    const int lane = tid & 31;
    const int row  = blockIdx.x * 8 + wid;      // 0..4095
    const int br   = row >> 11;
    const int d    = (row >> 8) & 7;
    const int w    = row & 255;

    const float* Msrc = (br ? M2 : M1) + (d * WDIM + w) * HDIM;
    const float* Bsrc = (br ? B2 : B1) + (d * WDIM + w) * HDIM;

    float m[8], b[8];
#pragma unroll
    for (int r = 0; r < 8; r++) {
        m[r] = Msrc[r * 32 + lane];     // coalesced across the warp
        b[r] = Bsrc[r * 32 + lane];
    }

    // Start line: argmax slope, tie-break max intercept.
    float cm = m[0], cb = b[0];
#pragma unroll
    for (int r = 1; r < 8; r++)
        if (m[r] > cm || (m[r] == cm && b[r] > cb)) { cm = m[r]; cb = b[r]; }
#pragma unroll
    for (int o = 16; o > 0; o >>= 1) {
        const float om = __shfl_xor_sync(~0u, cm, o);
        const float ob = __shfl_xor_sync(~0u, cb, o);
        if (om > cm || (om == cm && ob > cb)) { cm = om; cb = ob; }
    }

    const int    blk   = br * DPT + d;
    const size_t hbase = (size_t)blk * HDIM * WDIM + w;
    if (lane == 0) { g_hm[hbase] = cm; g_hb[hbase] = cb; }
    const float m0 = cm, b0 = cb;
    int k = 1;

    while (k < HDIM) {
        // Candidates: m_j < cm. Crossing q with current line; pick max q,
        // tie-break min slope (skips collinear intermediates).
        float bq = NEG_INF, bm = POS_INF, bb = 0.0f;
#pragma unroll
        for (int r = 0; r < 8; r++) {
            const float dm   = cm - m[r];
            const bool  cand = dm > 0.0f;
            const float qx   = cand ? __fdividef(b[r] - cb, dm) : NEG_INF;
            const float mx   = cand ? m[r] : POS_INF;
            if (qx > bq || (qx == bq && mx < bm)) { bq = qx; bm = mx; bb = b[r]; }
        }
#pragma unroll
        for (int o = 16; o > 0; o >>= 1) {
            const float oq = __shfl_xor_sync(~0u, bq, o);
            const float om = __shfl_xor_sync(~0u, bm, o);
            const float ob = __shfl_xor_sync(~0u, bb, o);
            if (oq > bq || (oq == bq && om < bm)) { bq = oq; bm = om; bb = ob; }
        }
        if (bq == NEG_INF) break;       // no line with smaller slope remains
        cm = bm; cb = bb;
        if (lane == 0) {
            g_hm[hbase + (size_t)k * WDIM] = cm;
            g_hb[hbase + (size_t)k * WDIM] = cb;
        }
        k++;
    }

    // Pad to a multiple of 4 with duplicates of line 0 (harmless under max).
    const int kpad = (k + 3) & ~3;
    for (int j = k + lane; j < kpad; j += 32) {
        g_hm[hbase + (size_t)j * WDIM] = m0;
        g_hb[hbase + (size_t)j * WDIM] = b0;
    }
    if (lane == 0) g_cnt[blk * WDIM + w] = kpad;
}

// ─────────── Kernel 2: scan over depth using hulls ─────────────────────────
__global__ __launch_bounds__(256)
void scan_kernel(const float* __restrict__ val, float* __restrict__ out)
{
    __shared__ float red[8][NB];
    __shared__ float q_s[NB];

    const int tid    = threadIdx.x;        // = w row
    const int wid    = tid >> 5;
    const int lane   = tid & 31;
    const int br     = blockIdx.y;
    const int batch0 = blockIdx.x * NB;

    float q[NB];
#pragma unroll
    for (int i = 0; i < NB; i++) q[i] = val[batch0 + i];

    // Hoist all per-depth counts + warp maxima off the critical path.
    int kk[DPT], km[DPT];
#pragma unroll
    for (int d = 0; d < DPT; d++)
        kk[d] = g_cnt[(br * DPT + d) * WDIM + tid];
#pragma unroll
    for (int d = 0; d < DPT; d++) {
        int x = kk[d];
#pragma unroll
        for (int o = 16; o > 0; o >>= 1)
            x = max(x, __shfl_xor_sync(~0u, x, o));
        km[d] = x;
    }

    for (int d = 0; d < DPT; d++) {
        const int k    = kk[d];
        const int kmax = km[d];

        float acc[NB];
#pragma unroll
        for (int i = 0; i < NB; i++) acc[i] = NEG_INF;

        const size_t hbase = (size_t)(br * DPT + d) * HDIM * WDIM + tid;
#pragma unroll 4
        for (int j = 0; j < kmax; j++) {
            float mj = g_hm[hbase + (size_t)j * WDIM];   // coalesced
            float bj = g_hb[hbase + (size_t)j * WDIM];
            const bool v = (j < k);
            mj = v ? mj : 0.0f;
            bj = v ? bj : NEG_INF;
#pragma unroll
            for (int i = 0; i < NB; i++)
                acc[i] = fmaxf(acc[i], fmaf(q[i], mj, bj));
        }

        // min over w: shfl within warp, then across the 8 warps via smem.
#pragma unroll
        for (int i = 0; i < NB; i++) {
            float v = acc[i];
#pragma unroll
            for (int o = 16; o > 0; o >>= 1)
                v = fminf(v, __shfl_xor_sync(~0u, v, o));
            if (lane == 0) red[wid][i] = v;
        }
        __syncthreads();
        if (tid < NB) {
            float v = red[0][tid];
#pragma unroll
            for (int ww = 1; ww < 8; ww++) v = fminf(v, red[ww][tid]);
            q_s[tid] = v;
        }
        __syncthreads();
#pragma unroll
        for (int i = 0; i < NB; i++) q[i] = q_s[i];
    }

    if (tid < NB)
        out[br * 1024 + batch0 + tid] = q_s[tid];
}

extern "C" void kernel_launch(void* const* d_in, const int* in_sizes, int n_in,
                              void* d_out, int out_size)
{
    const float* val = (const float*)d_in[0];
    const float* M1  = (const float*)d_in[1];
    const float* B1  = (const float*)d_in[2];
    const float* M2  = (const float*)d_in[3];
    const float* B2  = (const float*)d_in[4];
    float* out = (float*)d_out;

    hull_kernel<<<NROWS / 8, 256>>>(M1, B1, M2, B2);
    dim3 grid(1024 / NB, 2);
    scan_kernel<<<grid, 256>>>(val, out);
}

// round 11
// speedup vs baseline: 47.9177x; 1.1654x over previous
#include <cuda_runtime.h>
#include <cstdint>

#define WDIM 256
#define HDIM 256
#define DPT  8
#define NBLK (2 * DPT)                  // 16 (branch,depth) blocks
#define NROWS (NBLK * WDIM)             // 4096 hull rows
#define JGCAP 64                        // max line-groups of 4 (256 lines)
#define NEG_INF __int_as_float(0xff800000)
#define POS_INF __int_as_float(0x7f800000)
#define NB 2                            // batches per scan WARP

// Hull lines in groups of 4: [blk][jg][w] as float4 (coalesced LDG.128).
__device__ float4 g_m4[NBLK * JGCAP * WDIM];    // 4 MB
__device__ float4 g_b4[NBLK * JGCAP * WDIM];    // 4 MB
__device__ int    g_cnt[NBLK * WDIM];           // per-row padded count (x4)
__device__ int    g_jmax[NBLK];                 // per-block max count (atomicMax,
                                                // idempotent across replays)

// ─────────── Kernel 1: upper-envelope hull via warp-parallel Jarvis march ───
__global__ __launch_bounds__(256)
void hull_kernel(const float* __restrict__ M1, const float* __restrict__ B1,
                 const float* __restrict__ M2, const float* __restrict__ B2)
{
    const int tid  = threadIdx.x;
    const int wid  = tid >> 5;
    const int lane = tid & 31;
    const int row  = blockIdx.x * 8 + wid;      // 0..4095
    const int br   = row >> 11;
    const int d    = (row >> 8) & 7;
    const int w    = row & 255;

    const float* Msrc = (br ? M2 : M1) + (d * WDIM + w) * HDIM;
    const float* Bsrc = (br ? B2 : B1) + (d * WDIM + w) * HDIM;

    float m[8], b[8];
#pragma unroll
    for (int r = 0; r < 8; r++) {
        m[r] = Msrc[r * 32 + lane];     // coalesced across the warp
        b[r] = Bsrc[r * 32 + lane];
    }

    // Start line: argmax slope, tie-break max intercept.
    float cm = m[0], cb = b[0];
#pragma unroll
    for (int r = 1; r < 8; r++)
        if (m[r] > cm || (m[r] == cm && b[r] > cb)) { cm = m[r]; cb = b[r]; }
#pragma unroll
    for (int o = 16; o > 0; o >>= 1) {
        const float om = __shfl_xor_sync(~0u, cm, o);
        const float ob = __shfl_xor_sync(~0u, cb, o);
        if (om > cm || (om == cm && ob > cb)) { cm = om; cb = ob; }
    }

    const int blk = br * DPT + d;
    float* hm = (float*)g_m4;
    float* hb = (float*)g_b4;
    // float index of hull element j for this row:
    auto hidx = [&](int j) -> size_t {
        return ((size_t)(blk * JGCAP + (j >> 2)) * WDIM + w) * 4 + (j & 3);
    };

    if (lane == 0) { hm[hidx(0)] = cm; hb[hidx(0)] = cb; }
    const float m0 = cm, b0 = cb;
    int k = 1;

    while (k < HDIM) {
        // Candidates: m_j < cm. Crossing q with current line; pick max q,
        // tie-break min slope (skips collinear intermediates).
        float bq = NEG_INF, bm = POS_INF, bb = 0.0f;
#pragma unroll
        for (int r = 0; r < 8; r++) {
            const float dm   = cm - m[r];
            const bool  cand = dm > 0.0f;
            const float qx   = cand ? __fdividef(b[r] - cb, dm) : NEG_INF;
            const float mx   = cand ? m[r] : POS_INF;
            if (qx > bq || (qx == bq && mx < bm)) { bq = qx; bm = mx; bb = b[r]; }
        }
#pragma unroll
        for (int o = 16; o > 0; o >>= 1) {
            const float oq = __shfl_xor_sync(~0u, bq, o);
            const float om = __shfl_xor_sync(~0u, bm, o);
            const float ob = __shfl_xor_sync(~0u, bb, o);
            if (oq > bq || (oq == bq && om < bm)) { bq = oq; bm = om; bb = ob; }
        }
        if (bq == NEG_INF) break;       // no line with smaller slope remains
        cm = bm; cb = bb;
        if (lane == 0) { hm[hidx(k)] = cm; hb[hidx(k)] = cb; }
        k++;
    }

    // Pad to a multiple of 4 with duplicates of line 0 (harmless under max).
    const int kpad = (k + 3) & ~3;
    for (int j = k + lane; j < kpad; j += 32) {
        hm[hidx(j)] = m0;
        hb[hidx(j)] = b0;
    }
    if (lane == 0) {
        g_cnt[blk * WDIM + w] = kpad;
        atomicMax(&g_jmax[blk], kpad);   // zero-init global; idempotent
    }
}

// ─────────── Kernel 2: warp-autonomous scan (no CTA barriers) ───────────────
// Warp owns NB batches for one branch; lane owns w-rows {lane+32r, r<8}.
__global__ __launch_bounds__(128)
void scan_kernel(const float* __restrict__ val, float* __restrict__ out)
{
    const int lane = threadIdx.x & 31;
    const int wid  = threadIdx.x >> 5;
    const int gw   = blockIdx.x * 4 + wid;      // 0..1023
    const int br   = gw >> 9;
    const int batch0 = (gw & 511) * NB;

    float q[NB];
#pragma unroll
    for (int i = 0; i < NB; i++) q[i] = val[batch0 + i];

    for (int d = 0; d < DPT; d++) {
        const int blk = br * DPT + d;
        const int JG  = g_jmax[blk] >> 2;        // uniform line-group count

        int kr[8];
#pragma unroll
        for (int r = 0; r < 8; r++)
            kr[r] = g_cnt[blk * WDIM + lane + 32 * r];   // coalesced

        float rm[8][NB];
#pragma unroll
        for (int r = 0; r < 8; r++)
#pragma unroll
            for (int i = 0; i < NB; i++) rm[r][i] = NEG_INF;

        const size_t gb0 = (size_t)blk * JGCAP * WDIM + lane;
        for (int jg = 0; jg < JG; jg++) {
            const size_t gb = gb0 + (size_t)jg * WDIM;
#pragma unroll
            for (int r = 0; r < 8; r++) {
                float4 m4 = g_m4[gb + 32 * r];   // coalesced LDG.128
                float4 b4 = g_b4[gb + 32 * r];
                if (jg * 4 >= kr[r]) {           // tail group: neutral lines
                    m4.x = m4.y = m4.z = m4.w = 0.0f;
                    b4.x = b4.y = b4.z = b4.w = NEG_INF;
                }
#pragma unroll
                for (int i = 0; i < NB; i++) {
                    float t = fmaxf(fmaf(q[i], m4.x, b4.x),
                                    fmaf(q[i], m4.y, b4.y));
                    t = fmaxf(t, fmaf(q[i], m4.z, b4.z));
                    t = fmaxf(t, fmaf(q[i], m4.w, b4.w));
                    rm[r][i] = fmaxf(rm[r][i], t);
                }
            }
        }

        // min over this lane's 8 rows, then warp butterfly over 32 lanes.
#pragma unroll
        for (int i = 0; i < NB; i++) {
            float a = rm[0][i];
#pragma unroll
            for (int r = 1; r < 8; r++) a = fminf(a, rm[r][i]);
#pragma unroll
            for (int o = 16; o > 0; o >>= 1)
                a = fminf(a, __shfl_xor_sync(~0u, a, o));
            q[i] = a;                            // all lanes hold reduced q
        }
    }

    if (lane == 0) {
#pragma unroll
        for (int i = 0; i < NB; i++)
            out[br * 1024 + batch0 + i] = q[i];
    }
}

extern "C" void kernel_launch(void* const* d_in, const int* in_sizes, int n_in,
                              void* d_out, int out_size)
{
    const float* val = (const float*)d_in[0];
    const float* M1  = (const float*)d_in[1];
    const float* B1  = (const float*)d_in[2];
    const float* M2  = (const float*)d_in[3];
    const float* B2  = (const float*)d_in[4];
    float* out = (float*)d_out;

    hull_kernel<<<NROWS / 8, 256>>>(M1, B1, M2, B2);
    scan_kernel<<<2048 / (4 * NB), 128>>>(val, out);
}